// round 16
// baseline (speedup 1.0000x reference)
#include <cuda_runtime.h>
#include <cuda_fp16.h>

#define MAX_N 50000
#define MAX_E 800000
#define F1 128
#define F2 64

// -------- scratch --------
__device__ uint2 g_h1h[MAX_N * 32];   // h1 fp16: 128 halves/row
__device__ uint2 g_hrh[MAX_N * 32];   // relu(agg1) fp16: 128 halves/row
__device__ uint  g_h2h[MAX_N * 32];   // h2 fp16: 64 halves/row
__device__ float g_dinv[MAX_N];
__device__ int   g_cnt[MAX_N];        // stays zero between launches (scan re-zeroes)
__device__ int   g_rowptr[MAX_N + 1];
__device__ int   g_cursor[MAX_N];
__device__ uint2 g_edge[MAX_E];       // (src*32, half2(dinv[src],dinv[src]))

// -------- per-block local dtype detection (deterministic, no global state) --------
__device__ __forceinline__ int detect64(const void* ei, int E) {
    const long long* p = (const long long*)ei;
    int samples = E < 64 ? E : 64;
    int ok = 1;
#pragma unroll 8
    for (int i = 0; i < samples; i++) {
        long long v = p[i];
        if (v < 0 || v >= (long long)MAX_N) ok = 0;
    }
    return ok;   // 1 => data really is int64; 0 => int32 pairs
}

__device__ __forceinline__ int edge_at64(const void* ei, int idx, int is64) {
    if (is64) return (int)((const long long*)ei)[idx];
    return ((const int*)ei)[idx];
}

// -------- single-block scan (4/thread): rowptr, cursor, dinv; re-zeroes cnt --------
__global__ void scan_kernel(int n) {
    __shared__ int warpsum[32];
    __shared__ int carrysh;
    int t = threadIdx.x, lane = t & 31, w = t >> 5;
    if (t == 0) carrysh = 0;
    __syncthreads();
    int nIter = (n + 4095) / 4096;
    for (int it = 0; it < nIter; it++) {
        int i0 = it * 4096 + t * 4;
        int4 v = make_int4(0, 0, 0, 0);
        if (i0 + 3 < n) {
            v = *(const int4*)&g_cnt[i0];
            *(int4*)&g_cnt[i0] = make_int4(0, 0, 0, 0);
        } else {
            if (i0     < n) { v.x = g_cnt[i0];     g_cnt[i0]     = 0; }
            if (i0 + 1 < n) { v.y = g_cnt[i0 + 1]; g_cnt[i0 + 1] = 0; }
            if (i0 + 2 < n) { v.z = g_cnt[i0 + 2]; g_cnt[i0 + 2] = 0; }
            if (i0 + 3 < n) { v.w = g_cnt[i0 + 3]; g_cnt[i0 + 3] = 0; }
        }
        int s = v.x + v.y + v.z + v.w;
        int x = s;
#pragma unroll
        for (int o = 1; o < 32; o <<= 1) {
            int y = __shfl_up_sync(~0u, x, o);
            if (lane >= o) x += y;
        }
        if (lane == 31) warpsum[w] = x;
        __syncthreads();
        if (w == 0) {
            int s2 = warpsum[lane];
#pragma unroll
            for (int o = 1; o < 32; o <<= 1) {
                int y = __shfl_up_sync(~0u, s2, o);
                if (lane >= o) s2 += y;
            }
            warpsum[lane] = s2;
        }
        __syncthreads();
        int wbase = w ? warpsum[w - 1] : 0;
        int e0 = carrysh + wbase + x - s;
        int e1 = e0 + v.x, e2 = e1 + v.y, e3 = e2 + v.z;
        if (i0 < n)     { g_rowptr[i0]     = e0; g_cursor[i0]     = e0; g_dinv[i0]     = rsqrtf((float)(v.x + 1)); }
        if (i0 + 1 < n) { g_rowptr[i0 + 1] = e1; g_cursor[i0 + 1] = e1; g_dinv[i0 + 1] = rsqrtf((float)(v.y + 1)); }
        if (i0 + 2 < n) { g_rowptr[i0 + 2] = e2; g_cursor[i0 + 2] = e2; g_dinv[i0 + 2] = rsqrtf((float)(v.z + 1)); }
        if (i0 + 3 < n) { g_rowptr[i0 + 3] = e3; g_cursor[i0 + 3] = e3; g_dinv[i0 + 3] = rsqrtf((float)(v.w + 1)); }
        __syncthreads();
        if (t == 0) carrysh += warpsum[31];
        __syncthreads();
    }
    if (t == 0) g_rowptr[n] = carrysh;
}

// ======== fp16 tensor-core GEMM pieces (m16n8k16 + ldmatrix, swizzled smem) ========
__device__ __forceinline__ void ldsm_x4(unsigned& r0, unsigned& r1, unsigned& r2,
                                        unsigned& r3, unsigned addr) {
    asm volatile("ldmatrix.sync.aligned.m8n8.x4.shared.b16 {%0,%1,%2,%3},[%4];"
                 : "=r"(r0), "=r"(r1), "=r"(r2), "=r"(r3) : "r"(addr));
}
__device__ __forceinline__ void ldsm_x4_t(unsigned& r0, unsigned& r1, unsigned& r2,
                                          unsigned& r3, unsigned addr) {
    asm volatile("ldmatrix.sync.aligned.m8n8.x4.trans.shared.b16 {%0,%1,%2,%3},[%4];"
                 : "=r"(r0), "=r"(r1), "=r"(r2), "=r"(r3) : "r"(addr));
}
__device__ __forceinline__ void mma16816(float* c, unsigned a0, unsigned a1,
                                         unsigned a2, unsigned a3,
                                         unsigned b0, unsigned b1) {
    asm volatile(
        "mma.sync.aligned.m16n8k16.row.col.f32.f16.f16.f32 "
        "{%0,%1,%2,%3},{%4,%5,%6,%7},{%8,%9},{%0,%1,%2,%3};"
        : "+f"(c[0]), "+f"(c[1]), "+f"(c[2]), "+f"(c[3])
        : "r"(a0), "r"(a1), "r"(a2), "r"(a3), "r"(b0), "r"(b1));
}

__device__ __forceinline__ unsigned packh2(float a, float b) {
    __half2 h = __floats2half2_rn(a, b);
    return *(unsigned*)&h;
}

__device__ __forceinline__ uint4 loadChunk(const float* A, size_t off) {
    float4 v0 = *(const float4*)(A + off);
    float4 v1 = *(const float4*)(A + off + 4);
    uint4 u;
    u.x = packh2(v0.x, v0.y); u.y = packh2(v0.z, v0.w);
    u.z = packh2(v1.x, v1.y); u.w = packh2(v1.z, v1.w);
    return u;
}
__device__ __forceinline__ uint4 loadChunk(const __half* A, size_t off) {
    return *(const uint4*)(A + off);
}

// C[mt*128:+128, 0:BN] = A[.., 0:128] @ W[0:128, 0:BN]; K fully resident, 1 sync.
template<typename TA, int BN>
__device__ __forceinline__ void gemm16_body(const TA* __restrict__ A,
                                            const float* __restrict__ W,
                                            __half* __restrict__ C,
                                            int M, int mt) {
    constexpr int NCH = BN / 8;    // 16B chunks per B row
    constexpr int NG  = BN / 16;   // n-groups of 16 cols
    __shared__ uint4 sA4[2048];          // 128 x 16 chunks = 32KB
    __shared__ uint4 sB4[128 * NCH];     // 128 k-rows x NCH chunks
    int tid = threadIdx.x, lane = tid & 31, warp = tid >> 5;
    int rowBase = mt * 128;

#pragma unroll
    for (int c = tid; c < 2048; c += 256) {
        int row = c >> 4, kc = c & 15;
        int gr = rowBase + row;
        uint4 u = make_uint4(0, 0, 0, 0);
        if (gr < M) u = loadChunk(A, (size_t)gr * F1 + kc * 8);
        sA4[row * 16 + (kc ^ (row & 7))] = u;
    }
#pragma unroll
    for (int c = tid; c < 128 * NCH; c += 256) {
        int k = c / NCH, nc = c % NCH;
        const float* wp = W + (size_t)k * BN + nc * 8;
        float4 v0 = *(const float4*)wp;
        float4 v1 = *(const float4*)(wp + 4);
        uint4 u;
        u.x = packh2(v0.x, v0.y); u.y = packh2(v0.z, v0.w);
        u.z = packh2(v1.x, v1.y); u.w = packh2(v1.z, v1.w);
        sB4[k * NCH + (nc ^ (k & 7))] = u;
    }
    __syncthreads();

    float acc[2 * NG][4];
#pragma unroll
    for (int i = 0; i < 2 * NG; i++)
#pragma unroll
        for (int j = 0; j < 4; j++) acc[i][j] = 0.0f;

    unsigned sAb = (unsigned)__cvta_generic_to_shared(sA4);
    unsigned sBb = (unsigned)__cvta_generic_to_shared(sB4);
    int arow = warp * 16 + (lane & 15);
    int l8 = lane & 7, seg = lane >> 3;

#pragma unroll
    for (int ks = 0; ks < 8; ks++) {
        int akc = ks * 2 + (lane >> 4);
        unsigned a0, a1, a2, a3;
        ldsm_x4(a0, a1, a2, a3, sAb + ((unsigned)(arow * 16 + (akc ^ (arow & 7))) << 4));
        int bk = ks * 16 + (seg & 1) * 8 + l8;
#pragma unroll
        for (int ng = 0; ng < NG; ng++) {
            int bnc = ng * 2 + (seg >> 1);
            unsigned b0, b1, b2, b3;
            ldsm_x4_t(b0, b1, b2, b3, sBb + ((unsigned)(bk * NCH + (bnc ^ (bk & 7))) << 4));
            mma16816(acc[2 * ng],     a0, a1, a2, a3, b0, b1);
            mma16816(acc[2 * ng + 1], a0, a1, a2, a3, b2, b3);
        }
    }
    int g = lane >> 2, tig = lane & 3;
    int r0 = rowBase + warp * 16 + g, r1 = r0 + 8;
#pragma unroll
    for (int nt = 0; nt < 2 * NG; nt++) {
        int col = nt * 8 + 2 * tig;
        if (r0 < M) *(__half2*)&C[(size_t)r0 * BN + col] = __floats2half2_rn(acc[nt][0], acc[nt][1]);
        if (r1 < M) *(__half2*)&C[(size_t)r1 * BN + col] = __floats2half2_rn(acc[nt][2], acc[nt][3]);
    }
}

// -------- fused A: GEMM1 tiles [0,Gg) + histogram (local dtype detect) --------
__global__ void __launch_bounds__(256) fused_hist_gemm1_kernel(
    const float* __restrict__ A, const float* __restrict__ W,
    __half* __restrict__ C, int M, const void* ei, int E, int Gg) {
    if ((int)blockIdx.x < Gg) {
        gemm16_body<float, F1>(A, W, C, M, (int)blockIdx.x);
        return;
    }
    int is64 = detect64(ei, E);
    int idx = ((int)blockIdx.x - Gg) * 256 + threadIdx.x;
    int base = idx * 4;
    if (base >= E) return;
    if (!is64 && base + 3 < E) {
        const int* dp = (const int*)ei + E;
        int4 d = *(const int4*)(dp + base);
        atomicAdd(&g_cnt[d.x], 1);
        atomicAdd(&g_cnt[d.y], 1);
        atomicAdd(&g_cnt[d.z], 1);
        atomicAdd(&g_cnt[d.w], 1);
    } else {
#pragma unroll
        for (int q = 0; q < 4; q++) {
            int e = base + q;
            if (e < E) atomicAdd(&g_cnt[edge_at64(ei, E + e, is64)], 1);
        }
    }
}

// -------- fused B: remaining GEMM1 tiles + CSR build (edge records) --------
// record = (src*32, half2(dinv[src], dinv[src]))
__device__ __forceinline__ unsigned wpack(float ws) {
    __half2 h = __float2half2_rn(ws);
    return *(unsigned*)&h;
}

__global__ void __launch_bounds__(256) fused_build_gemm1_kernel(
    const float* __restrict__ A, const float* __restrict__ W,
    __half* __restrict__ C, int M, const void* ei, int E, int Gg, int mt0) {
    if ((int)blockIdx.x < Gg) {
        gemm16_body<float, F1>(A, W, C, M, mt0 + (int)blockIdx.x);
        return;
    }
    int is64 = detect64(ei, E);
    int idx = ((int)blockIdx.x - Gg) * 256 + threadIdx.x;
    int base = idx * 4;
    if (base >= E) return;
    if (!is64 && base + 3 < E) {
        const int* sp = (const int*)ei;
        int4 s = *(const int4*)(sp + base);
        int4 d = *(const int4*)(sp + E + base);
        float w0 = g_dinv[s.x], w1 = g_dinv[s.y], w2 = g_dinv[s.z], w3 = g_dinv[s.w];
        int p0 = atomicAdd(&g_cursor[d.x], 1);
        int p1 = atomicAdd(&g_cursor[d.y], 1);
        int p2 = atomicAdd(&g_cursor[d.z], 1);
        int p3 = atomicAdd(&g_cursor[d.w], 1);
        g_edge[p0] = make_uint2((unsigned)s.x * 32u, wpack(w0));
        g_edge[p1] = make_uint2((unsigned)s.y * 32u, wpack(w1));
        g_edge[p2] = make_uint2((unsigned)s.z * 32u, wpack(w2));
        g_edge[p3] = make_uint2((unsigned)s.w * 32u, wpack(w3));
    } else {
#pragma unroll
        for (int q = 0; q < 4; q++) {
            int e = base + q;
            if (e < E) {
                int s = edge_at64(ei, e, is64);
                int d = edge_at64(ei, E + e, is64);
                float ws = g_dinv[s];
                g_edge[atomicAdd(&g_cursor[d], 1)] = make_uint2((unsigned)s * 32u, wpack(ws));
            }
        }
    }
}

// -------- standalone GEMM2 (A fp16) --------
__global__ void __launch_bounds__(256) gemm2_kernel(
    const __half* __restrict__ A, const float* __restrict__ W,
    __half* __restrict__ C, int M) {
    gemm16_body<__half, F2>(A, W, C, M, (int)blockIdx.x);
}

// -------- agg layer 1: warp/node, HFMA2 inner, fp32 flush per 4 edges --------
__global__ void __launch_bounds__(256) agg1_kernel(const float* __restrict__ b1, int n) {
    int w    = (blockIdx.x * blockDim.x + threadIdx.x) >> 5;
    int lane = threadIdx.x & 31;
    if (w >= n) return;
    float di = g_dinv[w];
    uint2 uself = g_h1h[(unsigned)w * 32u + lane];
    float2 s0 = __half22float2(*(__half2*)&uself.x);
    float2 s1 = __half22float2(*(__half2*)&uself.y);
    float4 acc = make_float4(di * s0.x, di * s0.y, di * s1.x, di * s1.y);
    int j  = g_rowptr[w];
    int jE = g_rowptr[w + 1];
    const __half2 hz = __floats2half2_rn(0.0f, 0.0f);
    for (; j + 3 < jE; j += 4) {
        uint2 er[4];
#pragma unroll
        for (int q = 0; q < 4; q++) er[q] = g_edge[j + q];
        uint2 u[4];
#pragma unroll
        for (int q = 0; q < 4; q++) u[q] = g_h1h[er[q].x + lane];
        __half2 ha = hz, hb = hz;
#pragma unroll
        for (int q = 0; q < 4; q++) {
            __half2 wh = *(__half2*)&er[q].y;
            ha = __hfma2(wh, *(__half2*)&u[q].x, ha);
            hb = __hfma2(wh, *(__half2*)&u[q].y, hb);
        }
        float2 fa = __half22float2(ha), fb = __half22float2(hb);
        acc.x += fa.x; acc.y += fa.y;
        acc.z += fb.x; acc.w += fb.y;
    }
    for (; j < jE; j++) {
        uint2 rr = g_edge[j];
        float wa = __half22float2(*(__half2*)&rr.y).x;
        uint2 ua = g_h1h[rr.x + lane];
        float2 a0 = __half22float2(*(__half2*)&ua.x);
        float2 a1 = __half22float2(*(__half2*)&ua.y);
        acc.x += wa * a0.x; acc.y += wa * a0.y;
        acc.z += wa * a1.x; acc.w += wa * a1.y;
    }
    float4 bb = ((const float4*)b1)[lane];
    float rx = fmaxf(fmaf(acc.x, di, bb.x), 0.0f);
    float ry = fmaxf(fmaf(acc.y, di, bb.y), 0.0f);
    float rz = fmaxf(fmaf(acc.z, di, bb.z), 0.0f);
    float rw = fmaxf(fmaf(acc.w, di, bb.w), 0.0f);
    uint2 o;
    *(__half2*)&o.x = __floats2half2_rn(rx, ry);
    *(__half2*)&o.y = __floats2half2_rn(rz, rw);
    g_hrh[(unsigned)w * 32u + lane] = o;
}

// -------- agg layer 2: warp/node, HFMA2 inner, fp32 flush per 4 edges --------
__global__ void __launch_bounds__(256) agg2_kernel(const float* __restrict__ b2,
                                                   float* __restrict__ out, int n) {
    int w    = (blockIdx.x * blockDim.x + threadIdx.x) >> 5;
    int lane = threadIdx.x & 31;
    if (w >= n) return;
    float di = g_dinv[w];
    uint uself = g_h2h[(unsigned)w * 32u + lane];
    float2 sv = __half22float2(*(__half2*)&uself);
    float2 acc = make_float2(di * sv.x, di * sv.y);
    int j  = g_rowptr[w];
    int jE = g_rowptr[w + 1];
    const __half2 hz = __floats2half2_rn(0.0f, 0.0f);
    for (; j + 3 < jE; j += 4) {
        uint2 er[4];
#pragma unroll
        for (int q = 0; q < 4; q++) er[q] = g_edge[j + q];
        uint u[4];
#pragma unroll
        for (int q = 0; q < 4; q++) u[q] = g_h2h[er[q].x + lane];
        __half2 ha = hz;
#pragma unroll
        for (int q = 0; q < 4; q++) {
            __half2 wh = *(__half2*)&er[q].y;
            ha = __hfma2(wh, *(__half2*)&u[q], ha);
        }
        float2 fa = __half22float2(ha);
        acc.x += fa.x; acc.y += fa.y;
    }
    for (; j < jE; j++) {
        uint2 rr = g_edge[j];
        float wa = __half22float2(*(__half2*)&rr.y).x;
        uint ua = g_h2h[rr.x + lane];
        float2 fa = __half22float2(*(__half2*)&ua);
        acc.x += wa * fa.x; acc.y += wa * fa.y;
    }
    float2 bb = ((const float2*)b2)[lane];
    float2 r;
    r.x = fmaf(acc.x, di, bb.x);
    r.y = fmaf(acc.y, di, bb.y);
    ((float2*)out)[(unsigned)w * 32u + lane] = r;
}

extern "C" void kernel_launch(void* const* d_in, const int* in_sizes, int n_in,
                              void* d_out, int out_size) {
    const float* x  = (const float*)d_in[0];
    const void*  ei = d_in[1];
    const float* W1 = (const float*)d_in[2];
    const float* b1 = (const float*)d_in[3];
    const float* W2 = (const float*)d_in[4];
    const float* b2 = (const float*)d_in[5];
    float* out = (float*)d_out;

    int n = in_sizes[0] / F1;      // 50000
    int E = in_sizes[1] / 2;       // 800000

    void *p_h1h, *p_hrh, *p_h2h;
    cudaGetSymbolAddress(&p_h1h, g_h1h);
    cudaGetSymbolAddress(&p_hrh, g_hrh);
    cudaGetSymbolAddress(&p_h2h, g_h2h);

    int Gq  = (E + 1023) / 1024;              // aux blocks: 4 edges/thread
    int Gm  = (n + 127) / 128;                // 391 GEMM1 row tiles
    int Gm1 = (Gm * 2) / 5;                   // rows hidden behind hist
    int Gm2 = Gm - Gm1;                       // rows hidden behind build

    fused_hist_gemm1_kernel<<<Gm1 + Gq, 256>>>(x, W1, (__half*)p_h1h, n, ei, E, Gm1);
    scan_kernel<<<1, 1024>>>(n);
    fused_build_gemm1_kernel<<<Gm2 + Gq, 256>>>(x, W1, (__half*)p_h1h, n, ei, E, Gm2, Gm1);

    agg1_kernel<<<(n * 32 + 255) / 256, 256>>>(b1, n);
    gemm2_kernel<<<Gm, 256>>>((const __half*)p_hrh, W2, (__half*)p_h2h, n);
    agg2_kernel<<<(n * 32 + 255) / 256, 256>>>(b2, out, n);
}

// round 17
// speedup vs baseline: 1.0135x; 1.0135x over previous
#include <cuda_runtime.h>
#include <cuda_fp16.h>

#define MAX_N 50000
#define MAX_E 800000
#define F1 128
#define F2 64

// -------- scratch --------
__device__ uint2 g_h1h[MAX_N * 32];   // h1 fp16: 128 halves/row
__device__ uint2 g_hrh[MAX_N * 32];   // relu(agg1) fp16: 128 halves/row
__device__ uint  g_h2h[MAX_N * 32];   // h2 fp16: 64 halves/row
__device__ float g_dinv[MAX_N];
__device__ int   g_cnt[MAX_N];        // stays zero between launches (scan re-zeroes)
__device__ int   g_rowptr[MAX_N + 1];
__device__ int   g_cursor[MAX_N];
__device__ uint2 g_edge[MAX_E];       // (src*32, f32bits(dinv[src]))

// -------- per-block local dtype detection (deterministic, no global state) --------
__device__ __forceinline__ int detect64(const void* ei, int E) {
    const long long* p = (const long long*)ei;
    int samples = E < 64 ? E : 64;
    int ok = 1;
#pragma unroll 8
    for (int i = 0; i < samples; i++) {
        long long v = p[i];
        if (v < 0 || v >= (long long)MAX_N) ok = 0;
    }
    return ok;   // 1 => data really is int64; 0 => int32 pairs
}

__device__ __forceinline__ int edge_at64(const void* ei, int idx, int is64) {
    if (is64) return (int)((const long long*)ei)[idx];
    return ((const int*)ei)[idx];
}

// -------- single-block scan (4/thread): rowptr, cursor, dinv; re-zeroes cnt --------
__global__ void scan_kernel(int n) {
    __shared__ int warpsum[32];
    __shared__ int carrysh;
    int t = threadIdx.x, lane = t & 31, w = t >> 5;
    if (t == 0) carrysh = 0;
    __syncthreads();
    int nIter = (n + 4095) / 4096;
    for (int it = 0; it < nIter; it++) {
        int i0 = it * 4096 + t * 4;
        int4 v = make_int4(0, 0, 0, 0);
        if (i0 + 3 < n) {
            v = *(const int4*)&g_cnt[i0];
            *(int4*)&g_cnt[i0] = make_int4(0, 0, 0, 0);
        } else {
            if (i0     < n) { v.x = g_cnt[i0];     g_cnt[i0]     = 0; }
            if (i0 + 1 < n) { v.y = g_cnt[i0 + 1]; g_cnt[i0 + 1] = 0; }
            if (i0 + 2 < n) { v.z = g_cnt[i0 + 2]; g_cnt[i0 + 2] = 0; }
            if (i0 + 3 < n) { v.w = g_cnt[i0 + 3]; g_cnt[i0 + 3] = 0; }
        }
        int s = v.x + v.y + v.z + v.w;
        int x = s;
#pragma unroll
        for (int o = 1; o < 32; o <<= 1) {
            int y = __shfl_up_sync(~0u, x, o);
            if (lane >= o) x += y;
        }
        if (lane == 31) warpsum[w] = x;
        __syncthreads();
        if (w == 0) {
            int s2 = warpsum[lane];
#pragma unroll
            for (int o = 1; o < 32; o <<= 1) {
                int y = __shfl_up_sync(~0u, s2, o);
                if (lane >= o) s2 += y;
            }
            warpsum[lane] = s2;
        }
        __syncthreads();
        int wbase = w ? warpsum[w - 1] : 0;
        int e0 = carrysh + wbase + x - s;
        int e1 = e0 + v.x, e2 = e1 + v.y, e3 = e2 + v.z;
        if (i0 < n)     { g_rowptr[i0]     = e0; g_cursor[i0]     = e0; g_dinv[i0]     = rsqrtf((float)(v.x + 1)); }
        if (i0 + 1 < n) { g_rowptr[i0 + 1] = e1; g_cursor[i0 + 1] = e1; g_dinv[i0 + 1] = rsqrtf((float)(v.y + 1)); }
        if (i0 + 2 < n) { g_rowptr[i0 + 2] = e2; g_cursor[i0 + 2] = e2; g_dinv[i0 + 2] = rsqrtf((float)(v.z + 1)); }
        if (i0 + 3 < n) { g_rowptr[i0 + 3] = e3; g_cursor[i0 + 3] = e3; g_dinv[i0 + 3] = rsqrtf((float)(v.w + 1)); }
        __syncthreads();
        if (t == 0) carrysh += warpsum[31];
        __syncthreads();
    }
    if (t == 0) g_rowptr[n] = carrysh;
}

// ======== fp16 tensor-core GEMM pieces (m16n8k16 + ldmatrix, swizzled smem) ========
__device__ __forceinline__ void ldsm_x4(unsigned& r0, unsigned& r1, unsigned& r2,
                                        unsigned& r3, unsigned addr) {
    asm volatile("ldmatrix.sync.aligned.m8n8.x4.shared.b16 {%0,%1,%2,%3},[%4];"
                 : "=r"(r0), "=r"(r1), "=r"(r2), "=r"(r3) : "r"(addr));
}
__device__ __forceinline__ void ldsm_x4_t(unsigned& r0, unsigned& r1, unsigned& r2,
                                          unsigned& r3, unsigned addr) {
    asm volatile("ldmatrix.sync.aligned.m8n8.x4.trans.shared.b16 {%0,%1,%2,%3},[%4];"
                 : "=r"(r0), "=r"(r1), "=r"(r2), "=r"(r3) : "r"(addr));
}
__device__ __forceinline__ void mma16816(float* c, unsigned a0, unsigned a1,
                                         unsigned a2, unsigned a3,
                                         unsigned b0, unsigned b1) {
    asm volatile(
        "mma.sync.aligned.m16n8k16.row.col.f32.f16.f16.f32 "
        "{%0,%1,%2,%3},{%4,%5,%6,%7},{%8,%9},{%0,%1,%2,%3};"
        : "+f"(c[0]), "+f"(c[1]), "+f"(c[2]), "+f"(c[3])
        : "r"(a0), "r"(a1), "r"(a2), "r"(a3), "r"(b0), "r"(b1));
}

__device__ __forceinline__ unsigned packh2(float a, float b) {
    __half2 h = __floats2half2_rn(a, b);
    return *(unsigned*)&h;
}

__device__ __forceinline__ uint4 loadChunk(const float* A, size_t off) {
    float4 v0 = *(const float4*)(A + off);
    float4 v1 = *(const float4*)(A + off + 4);
    uint4 u;
    u.x = packh2(v0.x, v0.y); u.y = packh2(v0.z, v0.w);
    u.z = packh2(v1.x, v1.y); u.w = packh2(v1.z, v1.w);
    return u;
}
__device__ __forceinline__ uint4 loadChunk(const __half* A, size_t off) {
    return *(const uint4*)(A + off);
}

// C[mt*128:+128, 0:BN] = A[.., 0:128] @ W[0:128, 0:BN]; K fully resident, 1 sync.
template<typename TA, int BN>
__device__ __forceinline__ void gemm16_body(const TA* __restrict__ A,
                                            const float* __restrict__ W,
                                            __half* __restrict__ C,
                                            int M, int mt) {
    constexpr int NCH = BN / 8;    // 16B chunks per B row
    constexpr int NG  = BN / 16;   // n-groups of 16 cols
    __shared__ uint4 sA4[2048];          // 128 x 16 chunks = 32KB
    __shared__ uint4 sB4[128 * NCH];     // 128 k-rows x NCH chunks
    int tid = threadIdx.x, lane = tid & 31, warp = tid >> 5;
    int rowBase = mt * 128;

#pragma unroll
    for (int c = tid; c < 2048; c += 256) {
        int row = c >> 4, kc = c & 15;
        int gr = rowBase + row;
        uint4 u = make_uint4(0, 0, 0, 0);
        if (gr < M) u = loadChunk(A, (size_t)gr * F1 + kc * 8);
        sA4[row * 16 + (kc ^ (row & 7))] = u;
    }
#pragma unroll
    for (int c = tid; c < 128 * NCH; c += 256) {
        int k = c / NCH, nc = c % NCH;
        const float* wp = W + (size_t)k * BN + nc * 8;
        float4 v0 = *(const float4*)wp;
        float4 v1 = *(const float4*)(wp + 4);
        uint4 u;
        u.x = packh2(v0.x, v0.y); u.y = packh2(v0.z, v0.w);
        u.z = packh2(v1.x, v1.y); u.w = packh2(v1.z, v1.w);
        sB4[k * NCH + (nc ^ (k & 7))] = u;
    }
    __syncthreads();

    float acc[2 * NG][4];
#pragma unroll
    for (int i = 0; i < 2 * NG; i++)
#pragma unroll
        for (int j = 0; j < 4; j++) acc[i][j] = 0.0f;

    unsigned sAb = (unsigned)__cvta_generic_to_shared(sA4);
    unsigned sBb = (unsigned)__cvta_generic_to_shared(sB4);
    int arow = warp * 16 + (lane & 15);
    int l8 = lane & 7, seg = lane >> 3;

#pragma unroll
    for (int ks = 0; ks < 8; ks++) {
        int akc = ks * 2 + (lane >> 4);
        unsigned a0, a1, a2, a3;
        ldsm_x4(a0, a1, a2, a3, sAb + ((unsigned)(arow * 16 + (akc ^ (arow & 7))) << 4));
        int bk = ks * 16 + (seg & 1) * 8 + l8;
#pragma unroll
        for (int ng = 0; ng < NG; ng++) {
            int bnc = ng * 2 + (seg >> 1);
            unsigned b0, b1, b2, b3;
            ldsm_x4_t(b0, b1, b2, b3, sBb + ((unsigned)(bk * NCH + (bnc ^ (bk & 7))) << 4));
            mma16816(acc[2 * ng],     a0, a1, a2, a3, b0, b1);
            mma16816(acc[2 * ng + 1], a0, a1, a2, a3, b2, b3);
        }
    }
    int g = lane >> 2, tig = lane & 3;
    int r0 = rowBase + warp * 16 + g, r1 = r0 + 8;
#pragma unroll
    for (int nt = 0; nt < 2 * NG; nt++) {
        int col = nt * 8 + 2 * tig;
        if (r0 < M) *(__half2*)&C[(size_t)r0 * BN + col] = __floats2half2_rn(acc[nt][0], acc[nt][1]);
        if (r1 < M) *(__half2*)&C[(size_t)r1 * BN + col] = __floats2half2_rn(acc[nt][2], acc[nt][3]);
    }
}

// -------- fused A: GEMM1 tiles [0,Gg) + histogram (local dtype detect) --------
__global__ void __launch_bounds__(256) fused_hist_gemm1_kernel(
    const float* __restrict__ A, const float* __restrict__ W,
    __half* __restrict__ C, int M, const void* ei, int E, int Gg) {
    if ((int)blockIdx.x < Gg) {
        gemm16_body<float, F1>(A, W, C, M, (int)blockIdx.x);
        return;
    }
    int is64 = detect64(ei, E);
    int idx = ((int)blockIdx.x - Gg) * 256 + threadIdx.x;
    int base = idx * 4;
    if (base >= E) return;
    if (!is64 && base + 3 < E) {
        const int* dp = (const int*)ei + E;
        int4 d = *(const int4*)(dp + base);
        atomicAdd(&g_cnt[d.x], 1);
        atomicAdd(&g_cnt[d.y], 1);
        atomicAdd(&g_cnt[d.z], 1);
        atomicAdd(&g_cnt[d.w], 1);
    } else {
#pragma unroll
        for (int q = 0; q < 4; q++) {
            int e = base + q;
            if (e < E) atomicAdd(&g_cnt[edge_at64(ei, E + e, is64)], 1);
        }
    }
}

// -------- fused B: remaining GEMM1 tiles + CSR build (edge records) --------
// record = (src*32, f32bits(dinv[src]))
__global__ void __launch_bounds__(256) fused_build_gemm1_kernel(
    const float* __restrict__ A, const float* __restrict__ W,
    __half* __restrict__ C, int M, const void* ei, int E, int Gg, int mt0) {
    if ((int)blockIdx.x < Gg) {
        gemm16_body<float, F1>(A, W, C, M, mt0 + (int)blockIdx.x);
        return;
    }
    int is64 = detect64(ei, E);
    int idx = ((int)blockIdx.x - Gg) * 256 + threadIdx.x;
    int base = idx * 4;
    if (base >= E) return;
    if (!is64 && base + 3 < E) {
        const int* sp = (const int*)ei;
        int4 s = *(const int4*)(sp + base);
        int4 d = *(const int4*)(sp + E + base);
        float w0 = g_dinv[s.x], w1 = g_dinv[s.y], w2 = g_dinv[s.z], w3 = g_dinv[s.w];
        int p0 = atomicAdd(&g_cursor[d.x], 1);
        int p1 = atomicAdd(&g_cursor[d.y], 1);
        int p2 = atomicAdd(&g_cursor[d.z], 1);
        int p3 = atomicAdd(&g_cursor[d.w], 1);
        g_edge[p0] = make_uint2((unsigned)s.x * 32u, __float_as_uint(w0));
        g_edge[p1] = make_uint2((unsigned)s.y * 32u, __float_as_uint(w1));
        g_edge[p2] = make_uint2((unsigned)s.z * 32u, __float_as_uint(w2));
        g_edge[p3] = make_uint2((unsigned)s.w * 32u, __float_as_uint(w3));
    } else {
#pragma unroll
        for (int q = 0; q < 4; q++) {
            int e = base + q;
            if (e < E) {
                int s = edge_at64(ei, e, is64);
                int d = edge_at64(ei, E + e, is64);
                float ws = g_dinv[s];
                g_edge[atomicAdd(&g_cursor[d], 1)] = make_uint2((unsigned)s * 32u, __float_as_uint(ws));
            }
        }
    }
}

// -------- standalone GEMM2 (A fp16) --------
__global__ void __launch_bounds__(256) gemm2_kernel(
    const __half* __restrict__ A, const float* __restrict__ W,
    __half* __restrict__ C, int M) {
    gemm16_body<__half, F2>(A, W, C, M, (int)blockIdx.x);
}

// -------- agg layer 1: warp/node, fp32 FFMA, paired edge loads, 8-way MLP --------
__global__ void __launch_bounds__(256) agg1_kernel(const float* __restrict__ b1, int n) {
    int w    = (blockIdx.x * blockDim.x + threadIdx.x) >> 5;
    int lane = threadIdx.x & 31;
    if (w >= n) return;
    float di = g_dinv[w];
    uint2 uself = g_h1h[(unsigned)w * 32u + lane];
    float2 s0 = __half22float2(*(__half2*)&uself.x);
    float2 s1 = __half22float2(*(__half2*)&uself.y);
    float4 acc = make_float4(di * s0.x, di * s0.y, di * s1.x, di * s1.y);
    int j  = g_rowptr[w];
    int jE = g_rowptr[w + 1];

#define A1_EDGE(IDX, WBITS) do {                                  \
        float wa_ = __uint_as_float(WBITS);                        \
        uint2 ua_ = g_h1h[(IDX) + lane];                           \
        float2 f0_ = __half22float2(*(__half2*)&ua_.x);            \
        float2 f1_ = __half22float2(*(__half2*)&ua_.y);            \
        acc.x += wa_ * f0_.x; acc.y += wa_ * f0_.y;                \
        acc.z += wa_ * f1_.x; acc.w += wa_ * f1_.y;                \
    } while (0)

    if (j < jE && (j & 1)) {           // align to even for uint4 pairs
        uint2 rr = g_edge[j];
        A1_EDGE(rr.x, rr.y);
        j++;
    }
    const uint4* ep = (const uint4*)g_edge;      // 2 records per uint4
    for (; j + 7 < jE; j += 8) {
        uint4 e01 = ep[(j >> 1)];
        uint4 e23 = ep[(j >> 1) + 1];
        uint4 e45 = ep[(j >> 1) + 2];
        uint4 e67 = ep[(j >> 1) + 3];
        uint2 u0 = g_h1h[e01.x + lane], u1 = g_h1h[e01.z + lane];
        uint2 u2 = g_h1h[e23.x + lane], u3 = g_h1h[e23.z + lane];
        uint2 u4 = g_h1h[e45.x + lane], u5 = g_h1h[e45.z + lane];
        uint2 u6 = g_h1h[e67.x + lane], u7 = g_h1h[e67.z + lane];
        float w0 = __uint_as_float(e01.y), w1 = __uint_as_float(e01.w);
        float w2 = __uint_as_float(e23.y), w3 = __uint_as_float(e23.w);
        float w4 = __uint_as_float(e45.y), w5 = __uint_as_float(e45.w);
        float w6 = __uint_as_float(e67.y), w7 = __uint_as_float(e67.w);
        float2 a0 = __half22float2(*(__half2*)&u0.x), b0 = __half22float2(*(__half2*)&u0.y);
        float2 a1 = __half22float2(*(__half2*)&u1.x), b1v = __half22float2(*(__half2*)&u1.y);
        float2 a2 = __half22float2(*(__half2*)&u2.x), b2 = __half22float2(*(__half2*)&u2.y);
        float2 a3 = __half22float2(*(__half2*)&u3.x), b3 = __half22float2(*(__half2*)&u3.y);
        float2 a4 = __half22float2(*(__half2*)&u4.x), b4 = __half22float2(*(__half2*)&u4.y);
        float2 a5 = __half22float2(*(__half2*)&u5.x), b5 = __half22float2(*(__half2*)&u5.y);
        float2 a6 = __half22float2(*(__half2*)&u6.x), b6 = __half22float2(*(__half2*)&u6.y);
        float2 a7 = __half22float2(*(__half2*)&u7.x), b7 = __half22float2(*(__half2*)&u7.y);
        acc.x += w0 * a0.x + w1 * a1.x + w2 * a2.x + w3 * a3.x
               + w4 * a4.x + w5 * a5.x + w6 * a6.x + w7 * a7.x;
        acc.y += w0 * a0.y + w1 * a1.y + w2 * a2.y + w3 * a3.y
               + w4 * a4.y + w5 * a5.y + w6 * a6.y + w7 * a7.y;
        acc.z += w0 * b0.x + w1 * b1v.x + w2 * b2.x + w3 * b3.x
               + w4 * b4.x + w5 * b5.x + w6 * b6.x + w7 * b7.x;
        acc.w += w0 * b0.y + w1 * b1v.y + w2 * b2.y + w3 * b3.y
               + w4 * b4.y + w5 * b5.y + w6 * b6.y + w7 * b7.y;
    }
    if (j + 3 < jE) {
        uint4 e01 = ep[(j >> 1)];
        uint4 e23 = ep[(j >> 1) + 1];
        uint2 u0 = g_h1h[e01.x + lane], u1 = g_h1h[e01.z + lane];
        uint2 u2 = g_h1h[e23.x + lane], u3 = g_h1h[e23.z + lane];
        float w0 = __uint_as_float(e01.y), w1 = __uint_as_float(e01.w);
        float w2 = __uint_as_float(e23.y), w3 = __uint_as_float(e23.w);
        float2 a0 = __half22float2(*(__half2*)&u0.x), b0 = __half22float2(*(__half2*)&u0.y);
        float2 a1 = __half22float2(*(__half2*)&u1.x), b1v = __half22float2(*(__half2*)&u1.y);
        float2 a2 = __half22float2(*(__half2*)&u2.x), b2 = __half22float2(*(__half2*)&u2.y);
        float2 a3 = __half22float2(*(__half2*)&u3.x), b3 = __half22float2(*(__half2*)&u3.y);
        acc.x += w0 * a0.x + w1 * a1.x + w2 * a2.x + w3 * a3.x;
        acc.y += w0 * a0.y + w1 * a1.y + w2 * a2.y + w3 * a3.y;
        acc.z += w0 * b0.x + w1 * b1v.x + w2 * b2.x + w3 * b3.x;
        acc.w += w0 * b0.y + w1 * b1v.y + w2 * b2.y + w3 * b3.y;
        j += 4;
    }
    if (j + 1 < jE) {
        uint4 e01 = ep[(j >> 1)];
        uint2 u0 = g_h1h[e01.x + lane], u1 = g_h1h[e01.z + lane];
        float w0 = __uint_as_float(e01.y), w1 = __uint_as_float(e01.w);
        float2 a0 = __half22float2(*(__half2*)&u0.x), b0 = __half22float2(*(__half2*)&u0.y);
        float2 a1 = __half22float2(*(__half2*)&u1.x), b1v = __half22float2(*(__half2*)&u1.y);
        acc.x += w0 * a0.x + w1 * a1.x;
        acc.y += w0 * a0.y + w1 * a1.y;
        acc.z += w0 * b0.x + w1 * b1v.x;
        acc.w += w0 * b0.y + w1 * b1v.y;
        j += 2;
    }
    if (j < jE) {
        uint2 rr = g_edge[j];
        A1_EDGE(rr.x, rr.y);
    }
#undef A1_EDGE

    float4 bb = ((const float4*)b1)[lane];
    float rx = fmaxf(fmaf(acc.x, di, bb.x), 0.0f);
    float ry = fmaxf(fmaf(acc.y, di, bb.y), 0.0f);
    float rz = fmaxf(fmaf(acc.z, di, bb.z), 0.0f);
    float rw = fmaxf(fmaf(acc.w, di, bb.w), 0.0f);
    uint2 o;
    *(__half2*)&o.x = __floats2half2_rn(rx, ry);
    *(__half2*)&o.y = __floats2half2_rn(rz, rw);
    g_hrh[(unsigned)w * 32u + lane] = o;
}

// -------- agg layer 2: warp/node, fp32 FFMA, paired edge loads --------
__global__ void __launch_bounds__(256) agg2_kernel(const float* __restrict__ b2,
                                                   float* __restrict__ out, int n) {
    int w    = (blockIdx.x * blockDim.x + threadIdx.x) >> 5;
    int lane = threadIdx.x & 31;
    if (w >= n) return;
    float di = g_dinv[w];
    uint uself = g_h2h[(unsigned)w * 32u + lane];
    float2 sv = __half22float2(*(__half2*)&uself);
    float2 acc = make_float2(di * sv.x, di * sv.y);
    int j  = g_rowptr[w];
    int jE = g_rowptr[w + 1];

#define A2_EDGE(IDX, WBITS) do {                                  \
        float wa_ = __uint_as_float(WBITS);                        \
        uint ua_ = g_h2h[(IDX) + lane];                            \
        float2 f_ = __half22float2(*(__half2*)&ua_);               \
        acc.x += wa_ * f_.x; acc.y += wa_ * f_.y;                  \
    } while (0)

    if (j < jE && (j & 1)) {
        uint2 rr = g_edge[j];
        A2_EDGE(rr.x, rr.y);
        j++;
    }
    const uint4* ep = (const uint4*)g_edge;
    for (; j + 7 < jE; j += 8) {
        uint4 e01 = ep[(j >> 1)];
        uint4 e23 = ep[(j >> 1) + 1];
        uint4 e45 = ep[(j >> 1) + 2];
        uint4 e67 = ep[(j >> 1) + 3];
        uint u0 = g_h2h[e01.x + lane], u1 = g_h2h[e01.z + lane];
        uint u2 = g_h2h[e23.x + lane], u3 = g_h2h[e23.z + lane];
        uint u4 = g_h2h[e45.x + lane], u5 = g_h2h[e45.z + lane];
        uint u6 = g_h2h[e67.x + lane], u7 = g_h2h[e67.z + lane];
        float w0 = __uint_as_float(e01.y), w1 = __uint_as_float(e01.w);
        float w2 = __uint_as_float(e23.y), w3 = __uint_as_float(e23.w);
        float w4 = __uint_as_float(e45.y), w5 = __uint_as_float(e45.w);
        float w6 = __uint_as_float(e67.y), w7 = __uint_as_float(e67.w);
        float2 f0 = __half22float2(*(__half2*)&u0);
        float2 f1 = __half22float2(*(__half2*)&u1);
        float2 f2 = __half22float2(*(__half2*)&u2);
        float2 f3 = __half22float2(*(__half2*)&u3);
        float2 f4 = __half22float2(*(__half2*)&u4);
        float2 f5 = __half22float2(*(__half2*)&u5);
        float2 f6 = __half22float2(*(__half2*)&u6);
        float2 f7 = __half22float2(*(__half2*)&u7);
        acc.x += w0 * f0.x + w1 * f1.x + w2 * f2.x + w3 * f3.x
               + w4 * f4.x + w5 * f5.x + w6 * f6.x + w7 * f7.x;
        acc.y += w0 * f0.y + w1 * f1.y + w2 * f2.y + w3 * f3.y
               + w4 * f4.y + w5 * f5.y + w6 * f6.y + w7 * f7.y;
    }
    if (j + 3 < jE) {
        uint4 e01 = ep[(j >> 1)];
        uint4 e23 = ep[(j >> 1) + 1];
        uint u0 = g_h2h[e01.x + lane], u1 = g_h2h[e01.z + lane];
        uint u2 = g_h2h[e23.x + lane], u3 = g_h2h[e23.z + lane];
        float w0 = __uint_as_float(e01.y), w1 = __uint_as_float(e01.w);
        float w2 = __uint_as_float(e23.y), w3 = __uint_as_float(e23.w);
        float2 f0 = __half22float2(*(__half2*)&u0);
        float2 f1 = __half22float2(*(__half2*)&u1);
        float2 f2 = __half22float2(*(__half2*)&u2);
        float2 f3 = __half22float2(*(__half2*)&u3);
        acc.x += w0 * f0.x + w1 * f1.x + w2 * f2.x + w3 * f3.x;
        acc.y += w0 * f0.y + w1 * f1.y + w2 * f2.y + w3 * f3.y;
        j += 4;
    }
    if (j + 1 < jE) {
        uint4 e01 = ep[(j >> 1)];
        uint u0 = g_h2h[e01.x + lane], u1 = g_h2h[e01.z + lane];
        float w0 = __uint_as_float(e01.y), w1 = __uint_as_float(e01.w);
        float2 f0 = __half22float2(*(__half2*)&u0);
        float2 f1 = __half22float2(*(__half2*)&u1);
        acc.x += w0 * f0.x + w1 * f1.x;
        acc.y += w0 * f0.y + w1 * f1.y;
        j += 2;
    }
    if (j < jE) {
        uint2 rr = g_edge[j];
        A2_EDGE(rr.x, rr.y);
    }
#undef A2_EDGE

    float2 bb = ((const float2*)b2)[lane];
    float2 r;
    r.x = fmaf(acc.x, di, bb.x);
    r.y = fmaf(acc.y, di, bb.y);
    ((float2*)out)[(unsigned)w * 32u + lane] = r;
}

extern "C" void kernel_launch(void* const* d_in, const int* in_sizes, int n_in,
                              void* d_out, int out_size) {
    const float* x  = (const float*)d_in[0];
    const void*  ei = d_in[1];
    const float* W1 = (const float*)d_in[2];
    const float* b1 = (const float*)d_in[3];
    const float* W2 = (const float*)d_in[4];
    const float* b2 = (const float*)d_in[5];
    float* out = (float*)d_out;

    int n = in_sizes[0] / F1;      // 50000
    int E = in_sizes[1] / 2;       // 800000

    void *p_h1h, *p_hrh, *p_h2h;
    cudaGetSymbolAddress(&p_h1h, g_h1h);
    cudaGetSymbolAddress(&p_hrh, g_hrh);
    cudaGetSymbolAddress(&p_h2h, g_h2h);

    int Gq  = (E + 1023) / 1024;              // aux blocks: 4 edges/thread
    int Gm  = (n + 127) / 128;                // 391 GEMM1 row tiles
    int Gm1 = (Gm * 2) / 5;                   // rows hidden behind hist
    int Gm2 = Gm - Gm1;                       // rows hidden behind build

    fused_hist_gemm1_kernel<<<Gm1 + Gq, 256>>>(x, W1, (__half*)p_h1h, n, ei, E, Gm1);
    scan_kernel<<<1, 1024>>>(n);
    fused_build_gemm1_kernel<<<Gm2 + Gq, 256>>>(x, W1, (__half*)p_h1h, n, ei, E, Gm2, Gm1);

    agg1_kernel<<<(n * 32 + 255) / 256, 256>>>(b1, n);
    gemm2_kernel<<<Gm, 256>>>((const __half*)p_hrh, W2, (__half*)p_h2h, n);
    agg2_kernel<<<(n * 32 + 255) / 256, 256>>>(b2, out, n);
}